// round 4
// baseline (speedup 1.0000x reference)
#include <cuda_runtime.h>
#include <cuda_fp16.h>
#include <cstdint>

#define HW_N1 250000
#define HW_N2 300000
#define IMG_H 1408
#define IMG_W 1408

#define MT 128
#define NTHR 512
#define NCTA ((HW_N1 + MT - 1) / MT)   // 1954

#define ASTRIDE 520     // halves per A row (512 + 8 pad)
#define WSTRIDE 40      // halves per W row (32 + 8 pad)
#define NSTAGE 3

// SMEM byte offsets
#define OFF_A   0u
#define WBUF_SZ 20480u                  // 256*40*2
#define OFF_W   133120u                 // 128*520*2
#define OFF_IDX (OFF_W + NSTAGE * WBUF_SZ)   // 194560
#define SMEM_TOTAL (OFF_IDX + 512u)          // 195072

// ---------------- device globals (sanctioned scratch) ----------------
__device__ int    g_table[4 * IMG_H * IMG_W];
__device__ __half g_W16[256 * 1024];   // W1^T(256x512) | W2^T(256x256) | W3^T(256x256)
#define W1T_OFF 0
#define W2T_OFF (256 * 512)
#define W3T_OFF (256 * 512 + 256 * 256)

// ---------------- helpers ----------------
__device__ __forceinline__ uint32_t smem_u32(const void* p) {
    uint32_t a;
    asm("{ .reg .u64 t; cvta.to.shared.u64 t, %1; cvt.u32.u64 %0, t; }"
        : "=r"(a) : "l"(p));
    return a;
}
__device__ __forceinline__ void ldmatrix_x4(uint32_t* r, uint32_t addr) {
    asm volatile("ldmatrix.sync.aligned.m8n8.x4.shared.b16 {%0,%1,%2,%3}, [%4];"
                 : "=r"(r[0]), "=r"(r[1]), "=r"(r[2]), "=r"(r[3]) : "r"(addr));
}
__device__ __forceinline__ void mma16816(float* c, const uint32_t* a,
                                         uint32_t b0, uint32_t b1) {
    asm volatile(
        "mma.sync.aligned.m16n8k16.row.col.f32.f16.f16.f32 "
        "{%0,%1,%2,%3},{%4,%5,%6,%7},{%8,%9},{%0,%1,%2,%3};"
        : "+f"(c[0]), "+f"(c[1]), "+f"(c[2]), "+f"(c[3])
        : "r"(a[0]), "r"(a[1]), "r"(a[2]), "r"(a[3]), "r"(b0), "r"(b1));
}
__device__ __forceinline__ void cpasync16(uint32_t s, const void* g) {
    asm volatile("cp.async.cg.shared.global [%0], [%1], 16;" :: "r"(s), "l"(g));
}
#define CP_COMMIT() asm volatile("cp.async.commit_group;" ::: "memory")

// ---------------- prologue kernels ----------------
__global__ void build_table_kernel(const int* __restrict__ coords2) {
    int j = blockIdx.x * blockDim.x + threadIdx.x;
    if (j < HW_N2) {
        int b = coords2[3 * j + 0];
        int y = coords2[3 * j + 1];
        int x = coords2[3 * j + 2];
        g_table[b * (IMG_H * IMG_W) + y * IMG_W + x] = j;
    }
}

__global__ void conv_w_kernel(const float* __restrict__ W1,
                              const float* __restrict__ W2,
                              const float* __restrict__ W3) {
    int t = blockIdx.x * blockDim.x + threadIdx.x;   // 0 .. 256*1024-1
    if (t < 256 * 512) {
        int k = t >> 8, n = t & 255;
        g_W16[W1T_OFF + n * 512 + k] = __float2half_rn(W1[k * 256 + n]);
    } else if (t < 256 * 512 + 256 * 256) {
        int u = t - 256 * 512, k = u >> 8, n = u & 255;
        g_W16[W2T_OFF + n * 256 + k] = __float2half_rn(W2[k * 256 + n]);
    } else {
        int u = t - (256 * 512 + 256 * 256), k = u >> 8, n = u & 255;
        g_W16[W3T_OFF + n * 256 + k] = __float2half_rn(W3[k * 256 + n]);
    }
}

// ---------------- main fused kernel ----------------
__global__ void __launch_bounds__(NTHR, 1)
fused_mma_kernel(const float* __restrict__ feat1,
                 const float* __restrict__ feat2,
                 const int*   __restrict__ coords1,
                 float*       __restrict__ out)
{
    extern __shared__ char smem[];
    const uint32_t sb = smem_u32(smem);
    __half* sA   = (__half*)(smem + OFF_A);
    int*    sIdx = (int*)(smem + OFF_IDX);

    const int tid  = threadIdx.x;
    const int lane = tid & 31;
    const int wid  = tid >> 5;
    const int wm   = wid & 3;          // 0..3  (32 rows each)
    const int wn   = wid >> 2;         // 0..3  (64 cols each)
    const int row0 = blockIdx.x * MT;

    // join indices
    if (tid < MT) {
        int gr = min(row0 + tid, HW_N1 - 1);
        int b = coords1[3 * gr + 0];
        int y = coords1[3 * gr + 1];
        int x = coords1[3 * gr + 2];
        sIdx[tid] = g_table[b * (IMG_H * IMG_W) + y * IMG_W + x];
    }
    __syncthreads();

    // ---- load A = [mf1 | mf2] as fp16 into SMEM ----
    #pragma unroll
    for (int i = 0; i < 16; ++i) {
        int e  = tid + i * NTHR;
        int r  = e >> 6;
        int c4 = e & 63;
        int gr = min(row0 + r, HW_N1 - 1);
        float4 v = *(const float4*)(feat1 + (size_t)gr * 256 + c4 * 4);
        __half2 h0 = __floats2half2_rn(v.x, v.y);
        __half2 h1 = __floats2half2_rn(v.z, v.w);
        uint2 u = {*(uint32_t*)&h0, *(uint32_t*)&h1};
        *(uint2*)&sA[r * ASTRIDE + c4 * 4] = u;
    }
    #pragma unroll
    for (int i = 0; i < 16; ++i) {
        int e  = tid + i * NTHR;
        int r  = e >> 6;
        int c4 = e & 63;
        float4 v = *(const float4*)(feat2 + (size_t)sIdx[r] * 256 + c4 * 4);
        __half2 h0 = __floats2half2_rn(v.x, v.y);
        __half2 h1 = __floats2half2_rn(v.z, v.w);
        uint2 u = {*(uint32_t*)&h0, *(uint32_t*)&h1};
        *(uint2*)&sA[r * ASTRIDE + 256 + c4 * 4] = u;
    }
    __syncthreads();

    const int arow  = lane & 15;
    const int akoff = (lane >> 4) * 8;

    float acc[2][8][4];

    auto zero_acc = [&]() {
        #pragma unroll
        for (int tm = 0; tm < 2; tm++)
            #pragma unroll
            for (int j = 0; j < 8; j++)
                #pragma unroll
                for (int q = 0; q < 4; q++) acc[tm][j][q] = 0.f;
    };

    // one 32-k weight chunk: 256 n-rows x 32 k halves = 16 KB
    auto issueW = [&](const __half* wsrc, int wKdim, int c, int buf) {
        #pragma unroll
        for (int i = 0; i < 2; ++i) {
            int l    = tid * 2 + i;
            int n    = l >> 2;
            int kseg = l & 3;
            cpasync16(sb + OFF_W + (uint32_t)buf * WBUF_SZ + (n * WSTRIDE + kseg * 8) * 2,
                      wsrc + (size_t)n * wKdim + c * 32 + kseg * 8);
        }
        CP_COMMIT();
    };

    auto run_gemm = [&](const __half* wsrc, int wKdim, int nChunks, int aBase) {
        issueW(wsrc, wKdim, 0, 0);
        issueW(wsrc, wKdim, 1, 1);
        for (int c = 0; c < nChunks; ++c) {
            if (c + 1 < nChunks)
                asm volatile("cp.async.wait_group 1;" ::: "memory");
            else
                asm volatile("cp.async.wait_group 0;" ::: "memory");
            __syncthreads();
            // safe to overwrite buf (c+2)%3: all warps finished MMA(c-1)
            if (c + 2 < nChunks)
                issueW(wsrc, wKdim, c + 2, (c + 2) % NSTAGE);
            else
                CP_COMMIT();
            const uint32_t wbase = sb + OFF_W + (uint32_t)(c % NSTAGE) * WBUF_SZ;
            #pragma unroll
            for (int ks = 0; ks < 2; ++ks) {
                const int kbA = aBase + c * 32 + ks * 16;
                const int kbW = ks * 16;
                uint32_t a[2][4], b[4][4];
                #pragma unroll
                for (int tm = 0; tm < 2; ++tm)
                    ldmatrix_x4(a[tm],
                        sb + ((wm * 32 + tm * 16 + arow) * ASTRIDE + kbA + akoff) * 2);
                #pragma unroll
                for (int p = 0; p < 4; ++p)
                    ldmatrix_x4(b[p],
                        wbase + ((wn * 64 + p * 16 + arow) * WSTRIDE + kbW + akoff) * 2);
                #pragma unroll
                for (int tm = 0; tm < 2; ++tm)
                    #pragma unroll
                    for (int j = 0; j < 8; ++j)
                        mma16816(acc[tm][j], a[tm], b[j >> 1][j & 1], b[j >> 1][2 + (j & 1)]);
            }
        }
        __syncthreads();   // all MMA done before activations overwrite sA
    };

    auto store_act = [&](int dstBase) {
        #pragma unroll
        for (int tm = 0; tm < 2; ++tm) {
            int r0 = wm * 32 + tm * 16 + (lane >> 2);
            #pragma unroll
            for (int j = 0; j < 8; ++j) {
                int col = wn * 64 + j * 8 + (lane & 3) * 2;
                __half2 lo = __floats2half2_rn(fmaxf(acc[tm][j][0], 0.f),
                                               fmaxf(acc[tm][j][1], 0.f));
                __half2 hi = __floats2half2_rn(fmaxf(acc[tm][j][2], 0.f),
                                               fmaxf(acc[tm][j][3], 0.f));
                *(uint32_t*)&sA[r0 * ASTRIDE + dstBase + col]       = *(uint32_t*)&lo;
                *(uint32_t*)&sA[(r0 + 8) * ASTRIDE + dstBase + col] = *(uint32_t*)&hi;
            }
        }
    };

    // GEMM1: f1 = relu([mf1|mf2] @ W1), K=512
    zero_acc();
    run_gemm(g_W16 + W1T_OFF, 512, 16, 0);
    store_act(0);                      // f1 -> A cols [0,256)
    __syncthreads();

    // GEMM2: f2 = relu(f1 @ W2), K=256
    zero_acc();
    run_gemm(g_W16 + W2T_OFF, 256, 8, 0);
    store_act(256);                    // f2 -> A cols [256,512)
    __syncthreads();

    // GEMM3: f3 = f2 @ W3, K=256 (stays in registers)
    zero_acc();
    run_gemm(g_W16 + W3T_OFF, 256, 8, 256);

    // ---- epilogue: out = f1 * sigmoid(f3) + mf2 ----
    #pragma unroll
    for (int tm = 0; tm < 2; ++tm) {
        #pragma unroll
        for (int hh = 0; hh < 2; ++hh) {
            int rl   = wm * 32 + tm * 16 + (lane >> 2) + hh * 8;
            int grow = row0 + rl;
            if (grow < HW_N1) {
                const float* mrow = feat2 + (size_t)sIdx[rl] * 256;
                float* orow = out + (size_t)grow * 256;
                #pragma unroll
                for (int j = 0; j < 8; ++j) {
                    int col = wn * 64 + j * 8 + (lane & 3) * 2;
                    float x0 = acc[tm][j][hh * 2 + 0];
                    float x1 = acc[tm][j][hh * 2 + 1];
                    float a0 = 1.f / (1.f + __expf(-x0));
                    float a1 = 1.f / (1.f + __expf(-x1));
                    uint32_t f1u = *(uint32_t*)&sA[rl * ASTRIDE + col];
                    __half2 f1h = *(__half2*)&f1u;
                    float2 m = *(const float2*)(mrow + col);
                    float2 o;
                    o.x = __low2float(f1h)  * a0 + m.x;
                    o.y = __high2float(f1h) * a1 + m.y;
                    *(float2*)(orow + col) = o;
                }
            }
        }
    }
}

// ---------------- launch ----------------
extern "C" void kernel_launch(void* const* d_in, const int* in_sizes, int n_in,
                              void* d_out, int out_size) {
    const float* feat1   = (const float*)d_in[0];
    const float* feat2   = (const float*)d_in[1];
    const int*   coords1 = (const int*)d_in[2];
    const int*   coords2 = (const int*)d_in[3];
    const float* W1      = (const float*)d_in[4];
    const float* W2      = (const float*)d_in[5];
    const float* W3      = (const float*)d_in[6];
    float* out = (float*)d_out;

    build_table_kernel<<<(HW_N2 + 255) / 256, 256>>>(coords2);
    conv_w_kernel<<<(256 * 1024) / 256, 256>>>(W1, W2, W3);

    cudaFuncSetAttribute(fused_mma_kernel,
                         cudaFuncAttributeMaxDynamicSharedMemorySize, SMEM_TOTAL);
    fused_mma_kernel<<<NCTA, NTHR, SMEM_TOTAL>>>(feat1, feat2, coords1, out);
}

// round 5
// speedup vs baseline: 1.1300x; 1.1300x over previous
#include <cuda_runtime.h>
#include <cuda_fp16.h>
#include <cstdint>

#define HW_N1 250000
#define HW_N2 300000
#define IMG_H 1408
#define IMG_W 1408

#define MT 64
#define NCTA ((HW_N1 + MT - 1) / MT)   // 3907

#define ASTRIDE 520     // halves per A row (512 + 8 pad)
#define WSTRIDE 40      // halves per W row (32 + 8 pad)

// SMEM byte offsets
#define OFF_A   0u
#define OFF_W   66560u              // 64*520*2
#define WBUF_SZ 20480u              // 256*40*2
#define OFF_IDX 107520u             // 66560 + 2*20480
#define SMEM_TOTAL 107776u

// ---------------- device globals (sanctioned scratch) ----------------
__device__ int    g_table[4 * IMG_H * IMG_W];
__device__ __half g_W16[256 * 1024];   // W1^T(256x512) | W2^T(256x256) | W3^T(256x256)
#define W1T_OFF 0
#define W2T_OFF (256 * 512)
#define W3T_OFF (256 * 512 + 256 * 256)

// ---------------- helpers ----------------
__device__ __forceinline__ uint32_t smem_u32(const void* p) {
    uint32_t a;
    asm("{ .reg .u64 t; cvta.to.shared.u64 t, %1; cvt.u32.u64 %0, t; }"
        : "=r"(a) : "l"(p));
    return a;
}
__device__ __forceinline__ void ldmatrix_x4(uint32_t* r, uint32_t addr) {
    asm volatile("ldmatrix.sync.aligned.m8n8.x4.shared.b16 {%0,%1,%2,%3}, [%4];"
                 : "=r"(r[0]), "=r"(r[1]), "=r"(r[2]), "=r"(r[3]) : "r"(addr));
}
__device__ __forceinline__ void mma16816(float* c, const uint32_t* a,
                                         uint32_t b0, uint32_t b1) {
    asm volatile(
        "mma.sync.aligned.m16n8k16.row.col.f32.f16.f16.f32 "
        "{%0,%1,%2,%3},{%4,%5,%6,%7},{%8,%9},{%0,%1,%2,%3};"
        : "+f"(c[0]), "+f"(c[1]), "+f"(c[2]), "+f"(c[3])
        : "r"(a[0]), "r"(a[1]), "r"(a[2]), "r"(a[3]), "r"(b0), "r"(b1));
}
__device__ __forceinline__ void cpasync16(uint32_t s, const void* g) {
    asm volatile("cp.async.cg.shared.global [%0], [%1], 16;" :: "r"(s), "l"(g));
}
#define CP_COMMIT() asm volatile("cp.async.commit_group;" ::: "memory")

// ---------------- prologue kernels ----------------
__global__ void build_table_kernel(const int* __restrict__ coords2) {
    int j = blockIdx.x * blockDim.x + threadIdx.x;
    if (j < HW_N2) {
        int b = coords2[3 * j + 0];
        int y = coords2[3 * j + 1];
        int x = coords2[3 * j + 2];
        g_table[b * (IMG_H * IMG_W) + y * IMG_W + x] = j;
    }
}

__global__ void conv_w_kernel(const float* __restrict__ W1,
                              const float* __restrict__ W2,
                              const float* __restrict__ W3) {
    int t = blockIdx.x * blockDim.x + threadIdx.x;   // 0 .. 256*1024-1
    if (t < 256 * 512) {
        int k = t >> 8, n = t & 255;
        g_W16[W1T_OFF + n * 512 + k] = __float2half_rn(W1[k * 256 + n]);
    } else if (t < 256 * 512 + 256 * 256) {
        int u = t - 256 * 512, k = u >> 8, n = u & 255;
        g_W16[W2T_OFF + n * 256 + k] = __float2half_rn(W2[k * 256 + n]);
    } else {
        int u = t - (256 * 512 + 256 * 256), k = u >> 8, n = u & 255;
        g_W16[W3T_OFF + n * 256 + k] = __float2half_rn(W3[k * 256 + n]);
    }
}

// ---------------- main fused kernel ----------------
__global__ void __launch_bounds__(256, 2)
fused_mma_kernel(const float* __restrict__ feat1,
                 const float* __restrict__ feat2,
                 const int*   __restrict__ coords1,
                 float*       __restrict__ out)
{
    extern __shared__ char smem[];
    const uint32_t sb = smem_u32(smem);
    __half* sA   = (__half*)(smem + OFF_A);
    int*    sIdx = (int*)(smem + OFF_IDX);

    const int tid  = threadIdx.x;
    const int lane = tid & 31;
    const int wid  = tid >> 5;
    const int wm   = wid & 1;          // 0..1  (32 rows each)
    const int wn   = wid >> 1;         // 0..3  (64 cols each)
    const int row0 = blockIdx.x * MT;

    // join indices
    if (tid < MT) {
        int gr = min(row0 + tid, HW_N1 - 1);
        int b = coords1[3 * gr + 0];
        int y = coords1[3 * gr + 1];
        int x = coords1[3 * gr + 2];
        sIdx[tid] = g_table[b * (IMG_H * IMG_W) + y * IMG_W + x];
    }
    __syncthreads();

    // ---- load A = [mf1 | mf2] as fp16 into SMEM ----
    #pragma unroll
    for (int i = 0; i < 16; ++i) {
        int e  = tid + i * 256;
        int r  = e >> 6;
        int c4 = e & 63;
        int gr = min(row0 + r, HW_N1 - 1);
        float4 v = *(const float4*)(feat1 + (size_t)gr * 256 + c4 * 4);
        __half2 h0 = __floats2half2_rn(v.x, v.y);
        __half2 h1 = __floats2half2_rn(v.z, v.w);
        uint2 u = {*(uint32_t*)&h0, *(uint32_t*)&h1};
        *(uint2*)&sA[r * ASTRIDE + c4 * 4] = u;
    }
    #pragma unroll
    for (int i = 0; i < 16; ++i) {
        int e  = tid + i * 256;
        int r  = e >> 6;
        int c4 = e & 63;
        float4 v = *(const float4*)(feat2 + (size_t)sIdx[r] * 256 + c4 * 4);
        __half2 h0 = __floats2half2_rn(v.x, v.y);
        __half2 h1 = __floats2half2_rn(v.z, v.w);
        uint2 u = {*(uint32_t*)&h0, *(uint32_t*)&h1};
        *(uint2*)&sA[r * ASTRIDE + 256 + c4 * 4] = u;
    }

    const int arow  = lane & 15;
    const int akoff = (lane >> 4) * 8;

    float acc[2][8][4];

    auto zero_acc = [&]() {
        #pragma unroll
        for (int tm = 0; tm < 2; tm++)
            #pragma unroll
            for (int j = 0; j < 8; j++)
                #pragma unroll
                for (int q = 0; q < 4; q++) acc[tm][j][q] = 0.f;
    };

    auto issueW = [&](const __half* wsrc, int wKdim, int c, int buf) {
        #pragma unroll
        for (int i = 0; i < 4; ++i) {
            int l    = tid + i * 256;
            int n    = l >> 2;
            int kseg = l & 3;
            cpasync16(sb + OFF_W + (uint32_t)buf * WBUF_SZ + (n * WSTRIDE + kseg * 8) * 2,
                      wsrc + (size_t)n * wKdim + c * 32 + kseg * 8);
        }
        CP_COMMIT();
    };

    // Single __syncthreads per chunk:
    //   iter c: wait chunk c; sync (=> all warps done MMA(c-1));
    //   issue c+1 into buf (c+1)&1 (the one MMA(c-1) used — safe);
    //   MMA(c) on buf c&1. Trailing sync before caller touches sA.
    auto run_gemm = [&](const __half* wsrc, int wKdim, int nChunks, int aBase) {
        issueW(wsrc, wKdim, 0, 0);
        for (int c = 0; c < nChunks; ++c) {
            asm volatile("cp.async.wait_group 0;" ::: "memory");
            __syncthreads();
            if (c + 1 < nChunks)
                issueW(wsrc, wKdim, c + 1, (c + 1) & 1);
            const uint32_t wbase = sb + OFF_W + (uint32_t)(c & 1) * WBUF_SZ;
            #pragma unroll
            for (int ks = 0; ks < 2; ++ks) {
                const int kbA = aBase + c * 32 + ks * 16;
                const int kbW = ks * 16;
                uint32_t a[2][4], b[4][4];
                #pragma unroll
                for (int tm = 0; tm < 2; ++tm)
                    ldmatrix_x4(a[tm],
                        sb + ((wm * 32 + tm * 16 + arow) * ASTRIDE + kbA + akoff) * 2);
                #pragma unroll
                for (int p = 0; p < 4; ++p)
                    ldmatrix_x4(b[p],
                        wbase + ((wn * 64 + p * 16 + arow) * WSTRIDE + kbW + akoff) * 2);
                #pragma unroll
                for (int tm = 0; tm < 2; ++tm)
                    #pragma unroll
                    for (int j = 0; j < 8; ++j)
                        mma16816(acc[tm][j], a[tm], b[j >> 1][j & 1], b[j >> 1][2 + (j & 1)]);
            }
        }
        __syncthreads();   // all MMA done before caller overwrites sA
    };

    auto store_act = [&](int dstBase) {
        #pragma unroll
        for (int tm = 0; tm < 2; ++tm) {
            int r0 = wm * 32 + tm * 16 + (lane >> 2);
            #pragma unroll
            for (int j = 0; j < 8; ++j) {
                int col = wn * 64 + j * 8 + (lane & 3) * 2;
                __half2 lo = __floats2half2_rn(fmaxf(acc[tm][j][0], 0.f),
                                               fmaxf(acc[tm][j][1], 0.f));
                __half2 hi = __floats2half2_rn(fmaxf(acc[tm][j][2], 0.f),
                                               fmaxf(acc[tm][j][3], 0.f));
                *(uint32_t*)&sA[r0 * ASTRIDE + dstBase + col]       = *(uint32_t*)&lo;
                *(uint32_t*)&sA[(r0 + 8) * ASTRIDE + dstBase + col] = *(uint32_t*)&hi;
            }
        }
    };

    // GEMM1: f1 = relu([mf1|mf2] @ W1), K=512
    // NOTE: A-tile stores above are ordered by run_gemm's first in-loop sync.
    zero_acc();
    run_gemm(g_W16 + W1T_OFF, 512, 16, 0);
    store_act(0);                      // f1 -> A cols [0,256)

    // GEMM2: f2 = relu(f1 @ W2), K=256
    zero_acc();
    run_gemm(g_W16 + W2T_OFF, 256, 8, 0);
    store_act(256);                    // f2 -> A cols [256,512)

    // GEMM3: f3 = f2 @ W3, K=256 (stays in registers)
    zero_acc();
    run_gemm(g_W16 + W3T_OFF, 256, 8, 256);

    // ---- epilogue: out = f1 * sigmoid(f3) + mf2 ----
    #pragma unroll
    for (int tm = 0; tm < 2; ++tm) {
        #pragma unroll
        for (int hh = 0; hh < 2; ++hh) {
            int rl   = wm * 32 + tm * 16 + (lane >> 2) + hh * 8;
            int grow = row0 + rl;
            if (grow < HW_N1) {
                const float* mrow = feat2 + (size_t)sIdx[rl] * 256;
                float* orow = out + (size_t)grow * 256;
                #pragma unroll
                for (int j = 0; j < 8; ++j) {
                    int col = wn * 64 + j * 8 + (lane & 3) * 2;
                    float x0 = acc[tm][j][hh * 2 + 0];
                    float x1 = acc[tm][j][hh * 2 + 1];
                    float a0 = 1.f / (1.f + __expf(-x0));
                    float a1 = 1.f / (1.f + __expf(-x1));
                    uint32_t f1u = *(uint32_t*)&sA[rl * ASTRIDE + col];
                    __half2 f1h = *(__half2*)&f1u;
                    float2 m = *(const float2*)(mrow + col);
                    float2 o;
                    o.x = __low2float(f1h)  * a0 + m.x;
                    o.y = __high2float(f1h) * a1 + m.y;
                    *(float2*)(orow + col) = o;
                }
            }
        }
    }
}

// ---------------- launch ----------------
extern "C" void kernel_launch(void* const* d_in, const int* in_sizes, int n_in,
                              void* d_out, int out_size) {
    const float* feat1   = (const float*)d_in[0];
    const float* feat2   = (const float*)d_in[1];
    const int*   coords1 = (const int*)d_in[2];
    const int*   coords2 = (const int*)d_in[3];
    const float* W1      = (const float*)d_in[4];
    const float* W2      = (const float*)d_in[5];
    const float* W3      = (const float*)d_in[6];
    float* out = (float*)d_out;

    build_table_kernel<<<(HW_N2 + 255) / 256, 256>>>(coords2);
    conv_w_kernel<<<(256 * 1024) / 256, 256>>>(W1, W2, W3);

    cudaFuncSetAttribute(fused_mma_kernel,
                         cudaFuncAttributeMaxDynamicSharedMemorySize, SMEM_TOTAL);
    fused_mma_kernel<<<NCTA, 256, SMEM_TOTAL>>>(feat1, feat2, coords1, out);
}